// round 2
// baseline (speedup 1.0000x reference)
#include <cuda_runtime.h>
#include <cstdint>

typedef unsigned long long u64;

#define B_SZ 256
#define T_SZ 8192
#define PAIRS 4            // f32x2 pairs per thread (8 elements)
#define NTHR 128           // threads per block
#define ELEMS_PER_BLOCK (NTHR * PAIRS * 2)   // 1024

// Per-batch folded style constants:
// [0:8)  p1 = scale1*(w1-mean(w1))
// [8:16) q1 = scale1*(b1-mean(b1))
// [16:24) bias1
// [24:32) scale2  [32:40) bias2
// [40:48) scale3  [48:56) bias3
// [56:64) scale4  [64:72) bias4
__device__ float g_style[B_SZ * 72];

// ---------------- packed f32x2 helpers ----------------
__device__ __forceinline__ u64 pk2(float lo, float hi) {
    u64 r;
    asm("mov.b64 %0, {%1, %2};" : "=l"(r)
        : "r"(__float_as_uint(lo)), "r"(__float_as_uint(hi)));
    return r;
}
__device__ __forceinline__ void up2(u64 v, float& lo, float& hi) {
    unsigned a, b;
    asm("mov.b64 {%0, %1}, %2;" : "=r"(a), "=r"(b) : "l"(v));
    lo = __uint_as_float(a); hi = __uint_as_float(b);
}
__device__ __forceinline__ u64 dup2(float v) { return pk2(v, v); }
__device__ __forceinline__ u64 fma2(u64 a, u64 b, u64 c) {
    u64 d; asm("fma.rn.f32x2 %0, %1, %2, %3;" : "=l"(d) : "l"(a), "l"(b), "l"(c));
    return d;
}
__device__ __forceinline__ u64 mul2(u64 a, u64 b) {
    u64 d; asm("mul.rn.f32x2 %0, %1, %2;" : "=l"(d) : "l"(a), "l"(b));
    return d;
}
__device__ __forceinline__ u64 add2(u64 a, u64 b) {
    u64 d; asm("add.rn.f32x2 %0, %1, %2;" : "=l"(d) : "l"(a), "l"(b));
    return d;
}

// lrelu(y) = max(y, 0.01y) = 0.505*y + 0.495*|y|  (abs = 64-bit AND -> alu pipe)
__device__ __forceinline__ u64 lrelu2(u64 v, u64 c505, u64 c495) {
    u64 a = v & 0x7fffffff7fffffffULL;
    return fma2(c495, a, mul2(c505, v));
}

// 1 / (sqrt(max(var,0)) + 1e-6)
__device__ __forceinline__ float inv_sigma(float v) {
    v = fmaxf(v, 0.0f);
    float s; asm("sqrt.approx.f32 %0, %1;" : "=f"(s) : "f"(v));
    float r; asm("rcp.approx.f32 %0, %1;" : "=f"(r) : "f"(s + 1e-6f));
    return r;
}

// ---------------- style MLP + constant folding (one block per batch) --------
__global__ void style_k(const float* __restrict__ meta,
                        const float* __restrict__ mw1, const float* __restrict__ mb1,
                        const float* __restrict__ mw2, const float* __restrict__ mb2,
                        const float* __restrict__ mw3, const float* __restrict__ mb3,
                        const float* __restrict__ w1,  const float* __restrict__ b1)
{
    __shared__ float sm[16], s1[64], s2[128], ss[64];
    int b = blockIdx.x, t = threadIdx.x;
    if (t < 16) sm[t] = meta[b * 16 + t];
    __syncthreads();
    if (t < 64) {
        float a = mb1[t];
        #pragma unroll
        for (int k = 0; k < 16; k++) a += sm[k] * mw1[k * 64 + t];
        s1[t] = fmaxf(a, 0.0f);
    }
    __syncthreads();
    {
        float a = mb2[t];
        #pragma unroll 8
        for (int k = 0; k < 64; k++) a += s1[k] * mw2[k * 128 + t];
        s2[t] = fmaxf(a, 0.0f);
    }
    __syncthreads();
    if (t < 64) {
        float a = mb3[t];
        #pragma unroll 8
        for (int k = 0; k < 128; k++) a += s2[k] * mw3[k * 64 + t];
        ss[t] = a;
    }
    __syncthreads();
    if (t < 8) {
        int j = t;
        float wm = 0.f, bm = 0.f;
        #pragma unroll
        for (int i = 0; i < 8; i++) { wm += w1[i]; bm += b1[i]; }
        wm *= 0.125f; bm *= 0.125f;
        float u = w1[j] - wm, v = b1[j] - bm;
        float* st = g_style + b * 72;
        float sc1 = ss[2 * j], bi1 = ss[2 * j + 1];
        st[j]      = sc1 * u;
        st[8 + j]  = sc1 * v;
        st[16 + j] = bi1;
        st[24 + j] = ss[16 + 2 * j]; st[32 + j] = ss[16 + 2 * j + 1];
        st[40 + j] = ss[32 + 2 * j]; st[48 + j] = ss[32 + 2 * j + 1];
        st[56 + j] = ss[48 + 2 * j]; st[64 + j] = ss[48 + 2 * j + 1];
    }
}

// ---------------- mid layer: 8x8 matmul + AdaIN + lrelu, PAIRS interleaved --
__device__ __forceinline__ void mid_layer(u64 h[PAIRS][8],
                                          const u64* __restrict__ w,
                                          const u64* __restrict__ bias,
                                          const u64* __restrict__ asc,
                                          const u64* __restrict__ abi,
                                          u64 c505, u64 c495)
{
    u64 acc[PAIRS][8];
    #pragma unroll
    for (int j = 0; j < 8; j++) {
        u64 bj = bias[j];
        #pragma unroll
        for (int p = 0; p < PAIRS; p++) acc[p][j] = bj;
    }
    #pragma unroll
    for (int k = 0; k < 8; k++) {
        #pragma unroll
        for (int j = 0; j < 8; j++) {
            u64 wv = w[k * 8 + j];             // LDS.64 broadcast, reused x PAIRS
            #pragma unroll
            for (int p = 0; p < PAIRS; p++)
                acc[p][j] = fma2(h[p][k], wv, acc[p][j]);
        }
    }
    #pragma unroll
    for (int p = 0; p < PAIRS; p++) {
        u64 s1 = add2(add2(add2(acc[p][0], acc[p][1]), add2(acc[p][2], acc[p][3])),
                      add2(add2(acc[p][4], acc[p][5]), add2(acc[p][6], acc[p][7])));
        u64 s2 = mul2(acc[p][0], acc[p][0]);
        #pragma unroll
        for (int j = 1; j < 8; j++) s2 = fma2(acc[p][j], acc[p][j], s2);
        // var = s2/7 - s1^2/56   (ddof=1 over 8 channels)
        u64 var = fma2(s2, dup2(1.0f / 7.0f), mul2(mul2(s1, s1), dup2(-1.0f / 56.0f)));
        float v0, v1; up2(var, v0, v1);
        u64 inv = pk2(inv_sigma(v0), inv_sigma(v1));
        u64 negmu = mul2(s1, dup2(-0.125f));
        #pragma unroll
        for (int j = 0; j < 8; j++) {
            u64 g = mul2(asc[j], inv);         // scale * inv_sigma
            u64 d = fma2(g, negmu, abi[j]);    // bias - g*mu
            h[p][j] = lrelu2(fma2(g, acc[p][j], d), c505, c495);
        }
    }
}

// ---------------- main pointwise kernel ----------------
__global__ __launch_bounds__(NTHR)
void main_k(const float* __restrict__ x, float* __restrict__ out,
            const float* __restrict__ w1, const float* __restrict__ b1,
            const float* __restrict__ w2, const float* __restrict__ b2,
            const float* __restrict__ w3, const float* __restrict__ b3,
            const float* __restrict__ w4, const float* __restrict__ b4,
            const float* __restrict__ w5, const float* __restrict__ b5)
{
    __shared__ u64 sw2[64], sw3[64], sw4[64];
    __shared__ u64 sb2[8], sb3[8], sb4[8], sw5[8];
    __shared__ u64 sp1[8], sq1[8], sb1[8];
    __shared__ u64 ssc0[8], sbi0[8], ssc1[8], sbi1[8], ssc2[8], sbi2[8];
    __shared__ u64 sA, sB, sC, sb5;

    int tid = threadIdx.x;
    int b = blockIdx.y;

    if (tid < 64) {
        sw2[tid] = dup2(w2[tid]);
        sw3[tid] = dup2(w3[tid]);
        sw4[tid] = dup2(w4[tid]);
    }
    if (tid >= 64 && tid < 72) {
        int j = tid - 64;
        sb2[j] = dup2(b2[j]); sb3[j] = dup2(b3[j]); sb4[j] = dup2(b4[j]);
        sw5[j] = dup2(w5[j]);
        const float* st = g_style + b * 72;
        sp1[j]  = dup2(st[j]);      sq1[j]  = dup2(st[8 + j]);  sb1[j] = dup2(st[16 + j]);
        ssc0[j] = dup2(st[24 + j]); sbi0[j] = dup2(st[32 + j]);
        ssc1[j] = dup2(st[40 + j]); sbi1[j] = dup2(st[48 + j]);
        ssc2[j] = dup2(st[56 + j]); sbi2[j] = dup2(st[64 + j]);
    }
    if (tid == 80) {
        float wm = 0.f, bm = 0.f;
        #pragma unroll
        for (int i = 0; i < 8; i++) { wm += w1[i]; bm += b1[i]; }
        wm *= 0.125f; bm *= 0.125f;
        float A = 0.f, Bq = 0.f, Cq = 0.f;
        #pragma unroll
        for (int i = 0; i < 8; i++) {
            float u = w1[i] - wm, v = b1[i] - bm;
            A += u * u; Bq += u * v; Cq += v * v;
        }
        sA = dup2(A * (1.0f / 7.0f));
        sB = dup2(Bq * (2.0f / 7.0f));
        sC = dup2(Cq * (1.0f / 7.0f));
        sb5 = dup2(b5[0]);
    }
    __syncthreads();

    const u64 c505 = dup2(0.505f), c495 = dup2(0.495f);

    size_t base = (size_t)b * T_SZ + (size_t)blockIdx.x * ELEMS_PER_BLOCK + tid * (PAIRS * 2);
    const float4 xa = *reinterpret_cast<const float4*>(x + base);
    const float4 xb = *reinterpret_cast<const float4*>(x + base + 4);
    u64 xp[PAIRS] = { pk2(xa.x, xa.y), pk2(xa.z, xa.w),
                      pk2(xb.x, xb.y), pk2(xb.z, xb.w) };

    u64 h[PAIRS][8];
    u64 rA = sA, rB = sB, rC = sC;
    // layer 1 + adain1 collapsed: var is a quadratic in x; (h-mu) = u*x+v pre-scaled
    #pragma unroll
    for (int p = 0; p < PAIRS; p++) {
        u64 var = fma2(rA, mul2(xp[p], xp[p]), fma2(rB, xp[p], rC));
        float v0, v1; up2(var, v0, v1);
        u64 inv = pk2(inv_sigma(v0), inv_sigma(v1));
        #pragma unroll
        for (int j = 0; j < 8; j++)
            h[p][j] = lrelu2(fma2(fma2(sp1[j], xp[p], sq1[j]), inv, sb1[j]), c505, c495);
    }

    mid_layer(h, sw2, sb2, ssc0, sbi0, c505, c495);
    mid_layer(h, sw3, sb3, ssc1, sbi1, c505, c495);
    mid_layer(h, sw4, sb4, ssc2, sbi2, c505, c495);

    u64 o[PAIRS];
    u64 rb5 = sb5;
    #pragma unroll
    for (int p = 0; p < PAIRS; p++) {
        u64 acc = rb5;
        #pragma unroll
        for (int k = 0; k < 8; k++) acc = fma2(h[p][k], sw5[k], acc);
        o[p] = lrelu2(acc, c505, c495);
    }
    float a0, a1, a2, a3, a4, a5, a6, a7;
    up2(o[0], a0, a1); up2(o[1], a2, a3);
    up2(o[2], a4, a5); up2(o[3], a6, a7);
    *reinterpret_cast<float4*>(out + base)     = make_float4(a0, a1, a2, a3);
    *reinterpret_cast<float4*>(out + base + 4) = make_float4(a4, a5, a6, a7);
}

extern "C" void kernel_launch(void* const* d_in, const int* in_sizes, int n_in,
                              void* d_out, int out_size)
{
    const float* x    = (const float*)d_in[0];
    const float* meta = (const float*)d_in[1];
    const float* mw1  = (const float*)d_in[2];
    const float* mb1  = (const float*)d_in[3];
    const float* mw2  = (const float*)d_in[4];
    const float* mb2  = (const float*)d_in[5];
    const float* mw3  = (const float*)d_in[6];
    const float* mb3  = (const float*)d_in[7];
    const float* w1   = (const float*)d_in[8];
    const float* b1   = (const float*)d_in[9];
    const float* w2   = (const float*)d_in[10];
    const float* b2   = (const float*)d_in[11];
    const float* w3   = (const float*)d_in[12];
    const float* b3   = (const float*)d_in[13];
    const float* w4   = (const float*)d_in[14];
    const float* b4   = (const float*)d_in[15];
    const float* w5   = (const float*)d_in[16];
    const float* b5   = (const float*)d_in[17];
    float* out = (float*)d_out;

    style_k<<<B_SZ, 128>>>(meta, mw1, mb1, mw2, mb2, mw3, mb3, w1, b1);
    dim3 grid(T_SZ / ELEMS_PER_BLOCK, B_SZ);
    main_k<<<grid, NTHR>>>(x, out, w1, b1, w2, b2, w3, b3, w4, b4, w5, b5);
}

// round 3
// speedup vs baseline: 1.7801x; 1.7801x over previous
#include <cuda_runtime.h>
#include <cstdint>

typedef unsigned long long u64;

#define B_SZ 256
#define T_SZ 8192
#define PAIRS 2            // f32x2 pairs per thread (4 elements) -- R2 showed 4 pairs = MOV flood
#define NTHR 256
#define ELEMS_PER_BLOCK (NTHR * PAIRS * 2)   // 1024

// Per-batch folded style constants:
// [0:8)  p1 = scale1*(w1-mean(w1))
// [8:16) q1 = scale1*(b1-mean(b1))
// [16:24) bias1
// [24:32) scale2  [32:40) bias2
// [40:48) scale3  [48:56) bias3
// [56:64) scale4  [64:72) bias4
__device__ float g_style[B_SZ * 72];

// ---------------- packed f32x2 helpers ----------------
__device__ __forceinline__ u64 pk2(float lo, float hi) {
    u64 r;
    asm("mov.b64 %0, {%1, %2};" : "=l"(r)
        : "r"(__float_as_uint(lo)), "r"(__float_as_uint(hi)));
    return r;
}
__device__ __forceinline__ void up2(u64 v, float& lo, float& hi) {
    unsigned a, b;
    asm("mov.b64 {%0, %1}, %2;" : "=r"(a), "=r"(b) : "l"(v));
    lo = __uint_as_float(a); hi = __uint_as_float(b);
}
__device__ __forceinline__ u64 dup2(float v) { return pk2(v, v); }
__device__ __forceinline__ u64 fma2(u64 a, u64 b, u64 c) {
    u64 d; asm("fma.rn.f32x2 %0, %1, %2, %3;" : "=l"(d) : "l"(a), "l"(b), "l"(c));
    return d;
}
__device__ __forceinline__ u64 mul2(u64 a, u64 b) {
    u64 d; asm("mul.rn.f32x2 %0, %1, %2;" : "=l"(d) : "l"(a), "l"(b));
    return d;
}
__device__ __forceinline__ u64 add2(u64 a, u64 b) {
    u64 d; asm("add.rn.f32x2 %0, %1, %2;" : "=l"(d) : "l"(a), "l"(b));
    return d;
}

// lrelu(y) = max(y, 0.01y) = 0.505*y + 0.495*|y|  (abs = 64-bit AND -> alu pipe)
__device__ __forceinline__ u64 lrelu2(u64 v, u64 c505, u64 c495) {
    u64 a = v & 0x7fffffff7fffffffULL;
    return fma2(c495, a, mul2(c505, v));
}

// 1 / (sqrt(max(var,0)) + 1e-6)
__device__ __forceinline__ float inv_sigma(float v) {
    v = fmaxf(v, 0.0f);
    float s; asm("sqrt.approx.f32 %0, %1;" : "=f"(s) : "f"(v));
    float r; asm("rcp.approx.f32 %0, %1;" : "=f"(r) : "f"(s + 1e-6f));
    return r;
}

// ---------------- style MLP + constant folding (one block per batch) --------
__global__ void style_k(const float* __restrict__ meta,
                        const float* __restrict__ mw1, const float* __restrict__ mb1,
                        const float* __restrict__ mw2, const float* __restrict__ mb2,
                        const float* __restrict__ mw3, const float* __restrict__ mb3,
                        const float* __restrict__ w1,  const float* __restrict__ b1)
{
#if __CUDA_ARCH__ >= 900
    // Let the dependent main_k launch immediately; it synchronizes on our
    // completion (cudaGridDependencySynchronize) before touching g_style.
    cudaTriggerProgrammaticLaunchCompletion();
#endif
    __shared__ float sm[16], s1[64], s2[128], ss[64];
    int b = blockIdx.x, t = threadIdx.x;
    if (t < 16) sm[t] = meta[b * 16 + t];
    __syncthreads();
    if (t < 64) {
        float a = mb1[t];
        #pragma unroll
        for (int k = 0; k < 16; k++) a += sm[k] * mw1[k * 64 + t];
        s1[t] = fmaxf(a, 0.0f);
    }
    __syncthreads();
    {
        float a = mb2[t];
        #pragma unroll 16
        for (int k = 0; k < 64; k++) a += s1[k] * mw2[k * 128 + t];
        s2[t] = fmaxf(a, 0.0f);
    }
    __syncthreads();
    if (t < 64) {
        float a = mb3[t];
        #pragma unroll 16
        for (int k = 0; k < 128; k++) a += s2[k] * mw3[k * 64 + t];
        ss[t] = a;
    }
    __syncthreads();
    if (t < 8) {
        int j = t;
        float wm = 0.f, bm = 0.f;
        #pragma unroll
        for (int i = 0; i < 8; i++) { wm += w1[i]; bm += b1[i]; }
        wm *= 0.125f; bm *= 0.125f;
        float u = w1[j] - wm, v = b1[j] - bm;
        float* st = g_style + b * 72;
        float sc1 = ss[2 * j], bi1 = ss[2 * j + 1];
        st[j]      = sc1 * u;
        st[8 + j]  = sc1 * v;
        st[16 + j] = bi1;
        st[24 + j] = ss[16 + 2 * j]; st[32 + j] = ss[16 + 2 * j + 1];
        st[40 + j] = ss[32 + 2 * j]; st[48 + j] = ss[32 + 2 * j + 1];
        st[56 + j] = ss[48 + 2 * j]; st[64 + j] = ss[48 + 2 * j + 1];
    }
}

// ---------------- mid layer: 8x8 matmul + AdaIN + lrelu, PAIRS interleaved --
__device__ __forceinline__ void mid_layer(u64 h[PAIRS][8],
                                          const u64* __restrict__ w,
                                          const u64* __restrict__ bias,
                                          const u64* __restrict__ asc,
                                          const u64* __restrict__ abi,
                                          u64 c505, u64 c495)
{
    u64 acc[PAIRS][8];
    #pragma unroll
    for (int j = 0; j < 8; j++) {
        u64 bj = bias[j];
        #pragma unroll
        for (int p = 0; p < PAIRS; p++) acc[p][j] = bj;
    }
    #pragma unroll
    for (int k = 0; k < 8; k++) {
        #pragma unroll
        for (int j = 0; j < 8; j++) {
            u64 wv = w[k * 8 + j];             // LDS.64 broadcast, reused x PAIRS
            #pragma unroll
            for (int p = 0; p < PAIRS; p++)
                acc[p][j] = fma2(h[p][k], wv, acc[p][j]);
        }
    }
    #pragma unroll
    for (int p = 0; p < PAIRS; p++) {
        u64 s1 = add2(add2(add2(acc[p][0], acc[p][1]), add2(acc[p][2], acc[p][3])),
                      add2(add2(acc[p][4], acc[p][5]), add2(acc[p][6], acc[p][7])));
        u64 s2 = mul2(acc[p][0], acc[p][0]);
        #pragma unroll
        for (int j = 1; j < 8; j++) s2 = fma2(acc[p][j], acc[p][j], s2);
        // var = s2/7 - s1^2/56   (ddof=1 over 8 channels)
        u64 var = fma2(s2, dup2(1.0f / 7.0f), mul2(mul2(s1, s1), dup2(-1.0f / 56.0f)));
        float v0, v1; up2(var, v0, v1);
        u64 inv = pk2(inv_sigma(v0), inv_sigma(v1));
        u64 negmu = mul2(s1, dup2(-0.125f));
        #pragma unroll
        for (int j = 0; j < 8; j++) {
            u64 g = mul2(asc[j], inv);         // scale * inv_sigma
            u64 d = fma2(g, negmu, abi[j]);    // bias - g*mu
            h[p][j] = lrelu2(fma2(g, acc[p][j], d), c505, c495);
        }
    }
}

// ---------------- main pointwise kernel ----------------
__global__ __launch_bounds__(NTHR, 3)   // force regs <= 80 -> 3 blocks/SM resident
void main_k(const float* __restrict__ x, float* __restrict__ out,
            const float* __restrict__ w1, const float* __restrict__ b1,
            const float* __restrict__ w2, const float* __restrict__ b2,
            const float* __restrict__ w3, const float* __restrict__ b3,
            const float* __restrict__ w4, const float* __restrict__ b4,
            const float* __restrict__ w5, const float* __restrict__ b5)
{
    __shared__ u64 sw2[64], sw3[64], sw4[64];
    __shared__ u64 sb2[8], sb3[8], sb4[8], sw5[8];
    __shared__ u64 sp1[8], sq1[8], sb1[8];
    __shared__ u64 ssc0[8], sbi0[8], ssc1[8], sbi1[8], ssc2[8], sbi2[8];
    __shared__ u64 sA, sB, sC, sb5;

    int tid = threadIdx.x;
    int b = blockIdx.y;

    // ---- prologue: everything that does NOT depend on style_k ----
    if (tid < 64) {
        sw2[tid] = dup2(w2[tid]);
        sw3[tid] = dup2(w3[tid]);
        sw4[tid] = dup2(w4[tid]);
    }
    if (tid >= 64 && tid < 72) {
        int j = tid - 64;
        sb2[j] = dup2(b2[j]); sb3[j] = dup2(b3[j]); sb4[j] = dup2(b4[j]);
        sw5[j] = dup2(w5[j]);
    }
    if (tid == 80) {
        float wm = 0.f, bm = 0.f;
        #pragma unroll
        for (int i = 0; i < 8; i++) { wm += w1[i]; bm += b1[i]; }
        wm *= 0.125f; bm *= 0.125f;
        float A = 0.f, Bq = 0.f, Cq = 0.f;
        #pragma unroll
        for (int i = 0; i < 8; i++) {
            float u = w1[i] - wm, v = b1[i] - bm;
            A += u * u; Bq += u * v; Cq += v * v;
        }
        sA = dup2(A * (1.0f / 7.0f));
        sB = dup2(Bq * (2.0f / 7.0f));
        sC = dup2(Cq * (1.0f / 7.0f));
        sb5 = dup2(b5[0]);
    }

    size_t base = (size_t)b * T_SZ + (size_t)blockIdx.x * ELEMS_PER_BLOCK + tid * (PAIRS * 2);
    const float4 xa = *reinterpret_cast<const float4*>(x + base);
    u64 xp[PAIRS] = { pk2(xa.x, xa.y), pk2(xa.z, xa.w) };

#if __CUDA_ARCH__ >= 900
    // ---- wait for style_k results, then load them ----
    cudaGridDependencySynchronize();
#endif
    if (tid >= 64 && tid < 72) {
        int j = tid - 64;
        const float* st = g_style + b * 72;
        sp1[j]  = dup2(st[j]);      sq1[j]  = dup2(st[8 + j]);  sb1[j] = dup2(st[16 + j]);
        ssc0[j] = dup2(st[24 + j]); sbi0[j] = dup2(st[32 + j]);
        ssc1[j] = dup2(st[40 + j]); sbi1[j] = dup2(st[48 + j]);
        ssc2[j] = dup2(st[56 + j]); sbi2[j] = dup2(st[64 + j]);
    }
    __syncthreads();

    const u64 c505 = dup2(0.505f), c495 = dup2(0.495f);

    u64 h[PAIRS][8];
    u64 rA = sA, rB = sB, rC = sC;
    // layer 1 + adain1 collapsed: var is a quadratic in x; (h-mu) = u*x+v pre-scaled
    #pragma unroll
    for (int p = 0; p < PAIRS; p++) {
        u64 var = fma2(rA, mul2(xp[p], xp[p]), fma2(rB, xp[p], rC));
        float v0, v1; up2(var, v0, v1);
        u64 inv = pk2(inv_sigma(v0), inv_sigma(v1));
        #pragma unroll
        for (int j = 0; j < 8; j++)
            h[p][j] = lrelu2(fma2(fma2(sp1[j], xp[p], sq1[j]), inv, sb1[j]), c505, c495);
    }

    mid_layer(h, sw2, sb2, ssc0, sbi0, c505, c495);
    mid_layer(h, sw3, sb3, ssc1, sbi1, c505, c495);
    mid_layer(h, sw4, sb4, ssc2, sbi2, c505, c495);

    u64 o[PAIRS];
    u64 rb5 = sb5;
    #pragma unroll
    for (int p = 0; p < PAIRS; p++) {
        u64 acc = rb5;
        #pragma unroll
        for (int k = 0; k < 8; k++) acc = fma2(h[p][k], sw5[k], acc);
        o[p] = lrelu2(acc, c505, c495);
    }
    float a0, a1, a2, a3;
    up2(o[0], a0, a1); up2(o[1], a2, a3);
    *reinterpret_cast<float4*>(out + base) = make_float4(a0, a1, a2, a3);
}

extern "C" void kernel_launch(void* const* d_in, const int* in_sizes, int n_in,
                              void* d_out, int out_size)
{
    const float* x    = (const float*)d_in[0];
    const float* meta = (const float*)d_in[1];
    const float* mw1  = (const float*)d_in[2];
    const float* mb1  = (const float*)d_in[3];
    const float* mw2  = (const float*)d_in[4];
    const float* mb2  = (const float*)d_in[5];
    const float* mw3  = (const float*)d_in[6];
    const float* mb3  = (const float*)d_in[7];
    const float* w1   = (const float*)d_in[8];
    const float* b1   = (const float*)d_in[9];
    const float* w2   = (const float*)d_in[10];
    const float* b2   = (const float*)d_in[11];
    const float* w3   = (const float*)d_in[12];
    const float* b3   = (const float*)d_in[13];
    const float* w4   = (const float*)d_in[14];
    const float* b4   = (const float*)d_in[15];
    const float* w5   = (const float*)d_in[16];
    const float* b5   = (const float*)d_in[17];
    float* out = (float*)d_out;

    style_k<<<B_SZ, 128>>>(meta, mw1, mb1, mw2, mb2, mw3, mb3, w1, b1);

    // main_k launched with PDL: starts while style_k runs; grid-dependency
    // sync inside main_k orders the g_style reads.
    cudaLaunchConfig_t cfg = {};
    cfg.gridDim = dim3(T_SZ / ELEMS_PER_BLOCK, B_SZ);
    cfg.blockDim = dim3(NTHR);
    cfg.dynamicSmemBytes = 0;
    cfg.stream = 0;
    cudaLaunchAttribute attrs[1];
    attrs[0].id = cudaLaunchAttributeProgrammaticStreamSerialization;
    attrs[0].val.programmaticStreamSerializationAllowed = 1;
    cfg.attrs = attrs;
    cfg.numAttrs = 1;
    cudaLaunchKernelEx(&cfg, main_k, x, out, w1, b1, w2, b2, w3, b3, w4, b4, w5, b5);
}

// round 4
// speedup vs baseline: 1.8726x; 1.0519x over previous
#include <cuda_runtime.h>
#include <cstdint>

typedef unsigned long long u64;

#define B_SZ 256
#define T_SZ 8192
#define PAIRS 2            // f32x2 pairs per thread (4 elements)
#define NTHR 256
#define ELEMS_PER_BLOCK (NTHR * PAIRS * 2)   // 1024

// Per-batch folded style constants:
// [0:8)  p1 = scale1*(w1-mean(w1))
// [8:16) q1 = scale1*(b1-mean(b1))
// [16:24) bias1
// [24:32) scale2  [32:40) bias2
// [40:48) scale3  [48:56) bias3
// [56:64) scale4  [64:72) bias4
__device__ float g_style[B_SZ * 72];

// ---------------- packed f32x2 helpers ----------------
__device__ __forceinline__ u64 pk2(float lo, float hi) {
    u64 r;
    asm("mov.b64 %0, {%1, %2};" : "=l"(r)
        : "r"(__float_as_uint(lo)), "r"(__float_as_uint(hi)));
    return r;
}
__device__ __forceinline__ void up2(u64 v, float& lo, float& hi) {
    unsigned a, b;
    asm("mov.b64 {%0, %1}, %2;" : "=r"(a), "=r"(b) : "l"(v));
    lo = __uint_as_float(a); hi = __uint_as_float(b);
}
__device__ __forceinline__ u64 dup2(float v) { return pk2(v, v); }
__device__ __forceinline__ u64 fma2(u64 a, u64 b, u64 c) {
    u64 d; asm("fma.rn.f32x2 %0, %1, %2, %3;" : "=l"(d) : "l"(a), "l"(b), "l"(c));
    return d;
}
__device__ __forceinline__ u64 mul2(u64 a, u64 b) {
    u64 d; asm("mul.rn.f32x2 %0, %1, %2;" : "=l"(d) : "l"(a), "l"(b));
    return d;
}

// folded lrelu feeding a 0.505-prescaled matmul:  l~ = y + (0.495/0.505)*|y|
#define C98 0.980198019801980198f

// full lrelu (output layer only): 0.505*y + 0.495*|y|
__device__ __forceinline__ u64 lrelu2(u64 v, u64 c505, u64 c495) {
    u64 a = v & 0x7fffffff7fffffffULL;
    return fma2(c495, a, mul2(c505, v));
}
__device__ __forceinline__ u64 lrelu2f(u64 v, u64 c98) {   // folded form
    u64 a = v & 0x7fffffff7fffffffULL;
    return fma2(c98, a, v);
}

// ---------------- style MLP + constant folding (one block per batch) --------
__global__ void style_k(const float* __restrict__ meta,
                        const float* __restrict__ mw1, const float* __restrict__ mb1,
                        const float* __restrict__ mw2, const float* __restrict__ mb2,
                        const float* __restrict__ mw3, const float* __restrict__ mb3,
                        const float* __restrict__ w1,  const float* __restrict__ b1)
{
#if __CUDA_ARCH__ >= 900
    cudaTriggerProgrammaticLaunchCompletion();
#endif
    __shared__ float sm[16], s1[64], s2[128], ss[64];
    int b = blockIdx.x, t = threadIdx.x;
    if (t < 16) sm[t] = meta[b * 16 + t];
    __syncthreads();
    if (t < 64) {
        float a = mb1[t];
        #pragma unroll
        for (int k = 0; k < 16; k++) a += sm[k] * mw1[k * 64 + t];
        s1[t] = fmaxf(a, 0.0f);
    }
    __syncthreads();
    {
        float a = mb2[t];
        #pragma unroll 16
        for (int k = 0; k < 64; k++) a += s1[k] * mw2[k * 128 + t];
        s2[t] = fmaxf(a, 0.0f);
    }
    __syncthreads();
    if (t < 64) {
        float a = mb3[t];
        #pragma unroll 16
        for (int k = 0; k < 128; k++) a += s2[k] * mw3[k * 64 + t];
        ss[t] = a;
    }
    __syncthreads();
    if (t < 8) {
        int j = t;
        float wm = 0.f, bm = 0.f;
        #pragma unroll
        for (int i = 0; i < 8; i++) { wm += w1[i]; bm += b1[i]; }
        wm *= 0.125f; bm *= 0.125f;
        float u = w1[j] - wm, v = b1[j] - bm;
        float* st = g_style + b * 72;
        float sc1 = ss[2 * j], bi1 = ss[2 * j + 1];
        st[j]      = sc1 * u;
        st[8 + j]  = sc1 * v;
        st[16 + j] = bi1;
        st[24 + j] = ss[16 + 2 * j]; st[32 + j] = ss[16 + 2 * j + 1];
        st[40 + j] = ss[32 + 2 * j]; st[48 + j] = ss[32 + 2 * j + 1];
        st[56 + j] = ss[48 + 2 * j]; st[64 + j] = ss[48 + 2 * j + 1];
    }
}

// ---------------- mid layer: centered matmul + AdaIN + folded lrelu ---------
// Weights in smem are pre-centered over the output axis and pre-scaled by
// 0.505 (absorbing the previous layer's lrelu scale). The matmul therefore
// yields c = acc - mu directly; var = sum(c^2)/7, no mean pass needed.
__device__ __forceinline__ void mid_layer(u64 h[PAIRS][8],
                                          const u64* __restrict__ w,
                                          const u64* __restrict__ bias,
                                          const u64* __restrict__ asc,
                                          const u64* __restrict__ abi,
                                          u64 c98)
{
    u64 acc[PAIRS][8];
    #pragma unroll
    for (int j = 0; j < 8; j++) {
        u64 bj = bias[j];
        #pragma unroll
        for (int p = 0; p < PAIRS; p++) acc[p][j] = bj;
    }
    #pragma unroll
    for (int k = 0; k < 8; k++) {
        #pragma unroll
        for (int j = 0; j < 8; j++) {
            u64 wv = w[k * 8 + j];
            #pragma unroll
            for (int p = 0; p < PAIRS; p++)
                acc[p][j] = fma2(h[p][k], wv, acc[p][j]);
        }
    }
    #pragma unroll
    for (int p = 0; p < PAIRS; p++) {
        u64 s2 = mul2(acc[p][0], acc[p][0]);
        #pragma unroll
        for (int j = 1; j < 8; j++) s2 = fma2(acc[p][j], acc[p][j], s2);
        // inv = 1/(sqrt(s2/7) + 1e-6) = 1/(sqrt(s2)*rsqrt(7) + 1e-6); s2 >= 0
        float v0, v1; up2(s2, v0, v1);
        float q0, q1;
        asm("sqrt.approx.f32 %0, %1;" : "=f"(q0) : "f"(v0));
        asm("sqrt.approx.f32 %0, %1;" : "=f"(q1) : "f"(v1));
        float r0, r1;
        asm("rcp.approx.f32 %0, %1;" : "=f"(r0) : "f"(fmaf(0.377964473f, q0, 1e-6f)));
        asm("rcp.approx.f32 %0, %1;" : "=f"(r1) : "f"(fmaf(0.377964473f, q1, 1e-6f)));
        u64 inv = pk2(r0, r1);
        #pragma unroll
        for (int j = 0; j < 8; j++) {
            u64 cn = mul2(acc[p][j], inv);          // (acc-mu)/sigma
            u64 y  = fma2(asc[j], cn, abi[j]);      // scale*cn + bias
            h[p][j] = lrelu2f(y, c98);
        }
    }
}

// ---------------- main pointwise kernel ----------------
__global__ __launch_bounds__(NTHR, 3)
void main_k(const float* __restrict__ x, float* __restrict__ out,
            const float* __restrict__ w1, const float* __restrict__ b1,
            const float* __restrict__ w2, const float* __restrict__ b2,
            const float* __restrict__ w3, const float* __restrict__ b3,
            const float* __restrict__ w4, const float* __restrict__ b4,
            const float* __restrict__ w5, const float* __restrict__ b5)
{
    __shared__ u64 sw2[64], sw3[64], sw4[64];
    __shared__ u64 sb2[8], sb3[8], sb4[8], sw5[8];
    __shared__ u64 sp1[8], sq1[8], sb1[8];
    __shared__ u64 ssc0[8], sbi0[8], ssc1[8], sbi1[8], ssc2[8], sbi2[8];
    __shared__ u64 sA, sB, sC, sb5;

    int tid = threadIdx.x;
    int b = blockIdx.y;

    // ---- prologue (independent of style_k) ----
    // Center weights over output axis j and fold the 0.505 lrelu scale in.
    if (tid < 64) {
        float v2 = w2[tid], v3 = w3[tid], v4 = w4[tid];
        float m2 = v2, m3 = v3, m4 = v4;
        #pragma unroll
        for (int d = 1; d < 8; d <<= 1) {
            m2 += __shfl_xor_sync(0xffffffffu, m2, d);
            m3 += __shfl_xor_sync(0xffffffffu, m3, d);
            m4 += __shfl_xor_sync(0xffffffffu, m4, d);
        }
        sw2[tid] = dup2(0.505f * (v2 - m2 * 0.125f));
        sw3[tid] = dup2(0.505f * (v3 - m3 * 0.125f));
        sw4[tid] = dup2(0.505f * (v4 - m4 * 0.125f));
    }
    if (tid >= 64 && tid < 72) {
        int j = tid - 64;
        float m2 = 0.f, m3 = 0.f, m4 = 0.f;
        #pragma unroll
        for (int i = 0; i < 8; i++) { m2 += b2[i]; m3 += b3[i]; m4 += b4[i]; }
        sb2[j] = dup2(b2[j] - m2 * 0.125f);
        sb3[j] = dup2(b3[j] - m3 * 0.125f);
        sb4[j] = dup2(b4[j] - m4 * 0.125f);
        sw5[j] = dup2(0.505f * w5[j]);
    }
    if (tid == 80) {
        float wm = 0.f, bm = 0.f;
        #pragma unroll
        for (int i = 0; i < 8; i++) { wm += w1[i]; bm += b1[i]; }
        wm *= 0.125f; bm *= 0.125f;
        float A = 0.f, Bq = 0.f, Cq = 0.f;
        #pragma unroll
        for (int i = 0; i < 8; i++) {
            float u = w1[i] - wm, v = b1[i] - bm;
            A += u * u; Bq += u * v; Cq += v * v;
        }
        sA = dup2(A * (1.0f / 7.0f));
        sB = dup2(Bq * (2.0f / 7.0f));
        sC = dup2(Cq * (1.0f / 7.0f));
        sb5 = dup2(b5[0]);
    }

    size_t base = (size_t)b * T_SZ + (size_t)blockIdx.x * ELEMS_PER_BLOCK + tid * (PAIRS * 2);
    const float4 xa = *reinterpret_cast<const float4*>(x + base);
    u64 xp[PAIRS] = { pk2(xa.x, xa.y), pk2(xa.z, xa.w) };

#if __CUDA_ARCH__ >= 900
    cudaGridDependencySynchronize();
#endif
    if (tid >= 64 && tid < 72) {
        int j = tid - 64;
        const float* st = g_style + b * 72;
        sp1[j]  = dup2(st[j]);      sq1[j]  = dup2(st[8 + j]);  sb1[j] = dup2(st[16 + j]);
        ssc0[j] = dup2(st[24 + j]); sbi0[j] = dup2(st[32 + j]);
        ssc1[j] = dup2(st[40 + j]); sbi1[j] = dup2(st[48 + j]);
        ssc2[j] = dup2(st[56 + j]); sbi2[j] = dup2(st[64 + j]);
    }
    __syncthreads();

    const u64 c98 = dup2(C98);

    u64 h[PAIRS][8];
    u64 rA = sA, rB = sB, rC = sC;
    // layer 1 + adain1 collapsed: var = quadratic in x; (h-mu) pre-scaled in p1/q1
    #pragma unroll
    for (int p = 0; p < PAIRS; p++) {
        u64 var = fma2(rA, mul2(xp[p], xp[p]), fma2(rB, xp[p], rC));
        float v0, v1; up2(var, v0, v1);
        v0 = fmaxf(v0, 0.0f); v1 = fmaxf(v1, 0.0f);
        float q0, q1;
        asm("sqrt.approx.f32 %0, %1;" : "=f"(q0) : "f"(v0));
        asm("sqrt.approx.f32 %0, %1;" : "=f"(q1) : "f"(v1));
        float r0, r1;
        asm("rcp.approx.f32 %0, %1;" : "=f"(r0) : "f"(q0 + 1e-6f));
        asm("rcp.approx.f32 %0, %1;" : "=f"(r1) : "f"(q1 + 1e-6f));
        u64 inv = pk2(r0, r1);
        #pragma unroll
        for (int j = 0; j < 8; j++) {
            u64 y = fma2(fma2(sp1[j], xp[p], sq1[j]), inv, sb1[j]);
            h[p][j] = lrelu2f(y, c98);
        }
    }

    mid_layer(h, sw2, sb2, ssc0, sbi0, c98);
    mid_layer(h, sw3, sb3, ssc1, sbi1, c98);
    mid_layer(h, sw4, sb4, ssc2, sbi2, c98);

    const u64 c505 = dup2(0.505f), c495 = dup2(0.495f);
    u64 o[PAIRS];
    u64 rb5 = sb5;
    #pragma unroll
    for (int p = 0; p < PAIRS; p++) {
        u64 acc = rb5;
        #pragma unroll
        for (int k = 0; k < 8; k++) acc = fma2(h[p][k], sw5[k], acc);
        o[p] = lrelu2(acc, c505, c495);     // final lrelu: exact form
    }
    float a0, a1, a2, a3;
    up2(o[0], a0, a1); up2(o[1], a2, a3);
    *reinterpret_cast<float4*>(out + base) = make_float4(a0, a1, a2, a3);
}

extern "C" void kernel_launch(void* const* d_in, const int* in_sizes, int n_in,
                              void* d_out, int out_size)
{
    const float* x    = (const float*)d_in[0];
    const float* meta = (const float*)d_in[1];
    const float* mw1  = (const float*)d_in[2];
    const float* mb1  = (const float*)d_in[3];
    const float* mw2  = (const float*)d_in[4];
    const float* mb2  = (const float*)d_in[5];
    const float* mw3  = (const float*)d_in[6];
    const float* mb3  = (const float*)d_in[7];
    const float* w1   = (const float*)d_in[8];
    const float* b1   = (const float*)d_in[9];
    const float* w2   = (const float*)d_in[10];
    const float* b2   = (const float*)d_in[11];
    const float* w3   = (const float*)d_in[12];
    const float* b3   = (const float*)d_in[13];
    const float* w4   = (const float*)d_in[14];
    const float* b4   = (const float*)d_in[15];
    const float* w5   = (const float*)d_in[16];
    const float* b5   = (const float*)d_in[17];
    float* out = (float*)d_out;

    style_k<<<B_SZ, 128>>>(meta, mw1, mb1, mw2, mb2, mw3, mb3, w1, b1);

    cudaLaunchConfig_t cfg = {};
    cfg.gridDim = dim3(T_SZ / ELEMS_PER_BLOCK, B_SZ);
    cfg.blockDim = dim3(NTHR);
    cfg.dynamicSmemBytes = 0;
    cfg.stream = 0;
    cudaLaunchAttribute attrs[1];
    attrs[0].id = cudaLaunchAttributeProgrammaticStreamSerialization;
    attrs[0].val.programmaticStreamSerializationAllowed = 1;
    cfg.attrs = attrs;
    cfg.numAttrs = 1;
    cudaLaunchKernelEx(&cfg, main_k, x, out, w1, b1, w2, b2, w3, b3, w4, b4, w5, b5);
}